// round 8
// baseline (speedup 1.0000x reference)
#include <cuda_runtime.h>
#include <cstdint>
#include <cstddef>

#define BB 256
#define TT 256
#define II 512
#define HH 1024

#define NTHREADS 256
#define NCTA 128
#define HALFC 64

// ---- loop-phase dynamic smem layout (float offsets) ----
#define L_A      0
#define L_A_BUF  (128*72)            // A stage: 128 x 64, stride 72
#define L_W      (2*L_A_BUF)         // 18432
#define L_W_BUF  (64*264)            // W slice: 64 x 256, stride 264
#define L_BI     (L_W + 2*L_W_BUF)   // 52224
#define L_BI_BUF 16
#define SMEM_FLOATS (L_BI + 2*L_BI_BUF)  // 52256
#define SMEM_BYTES  (SMEM_FLOATS*4)      // 209024 B

// own-partial staging buffer (aliases A stage region, used post-GEMM)
#define L_OWN    L_A                 // 128 x 16, stride 18 (2304 floats)

// ---- prologue-phase aliased smem layout (temporally disjoint) ----
#define P_A      0
#define P_A_BUF  (256*36)
#define P_W      (2*P_A_BUF)
#define P_W_BUF  (128*36)

// ---- persistent device state ----
__device__ float    g_h[2][BB * HH];                 // double-buffered h (tf32 bits, pair-permuted cols)
__device__ float    g_part[2][2 * 64 * 8192];        // [parity][(half*64+lh)*8192]
__device__ float    g_xpart[(size_t)TT * BB * HH];   // precomputed x@Wx^T (sorted rows, linear cols)
__device__ unsigned g_cnt[3];
__device__ unsigned g_gen[3];
__device__ unsigned g_pflag[2][16];                  // partial producers per nblk
__device__ unsigned g_hflag[2][16];                  // h reducers per 64-col group

// ---- grid barrier ----
__device__ __forceinline__ void gbar(int idx, unsigned count) {
    __threadfence();
    __syncthreads();
    if (threadIdx.x == 0) {
        volatile unsigned* vg = (volatile unsigned*)&g_gen[idx];
        unsigned g = *vg;
        unsigned old = atomicAdd(&g_cnt[idx], 1u);
        if (old == count - 1) {
            g_cnt[idx] = 0;
            __threadfence();
            *vg = g + 1;
        } else {
            while (*vg == g) {}
            __threadfence();
        }
    }
    __syncthreads();
}

// ---- monotonic flag sync ----
__device__ __forceinline__ void arrive(unsigned* f) {
    __threadfence();
    __syncthreads();
    if (threadIdx.x == 0) atomicAdd(f, 1u);
}
__device__ __forceinline__ void waitflag(unsigned* f, unsigned target) {
    __syncthreads();
    if (threadIdx.x == 0) {
        volatile unsigned* vf = (volatile unsigned*)f;
        while (*vf < target) {}
        __threadfence();
    }
    __syncthreads();
}

// ---- helpers ----
__device__ __forceinline__ void cpa(float* dst, const float* src) {
    uint32_t d = (uint32_t)__cvta_generic_to_shared(dst);
    asm volatile("cp.async.cg.shared.global [%0], [%1], 16;" :: "r"(d), "l"(src));
}
#define CPCOMMIT() asm volatile("cp.async.commit_group;")
#define CPWAIT(n)  asm volatile("cp.async.wait_group %0;" :: "n"(n))

__device__ __forceinline__ uint32_t f2tf(float f) {
    uint32_t u; asm volatile("cvt.rna.tf32.f32 %0, %1;" : "=r"(u) : "f"(f)); return u;
}
__device__ __forceinline__ void mma8(float* c, uint32_t a0, uint32_t a1,
                                     uint32_t a2, uint32_t a3,
                                     uint32_t b0, uint32_t b1) {
    asm volatile(
        "mma.sync.aligned.m16n8k8.row.col.f32.tf32.tf32.f32 "
        "{%0,%1,%2,%3},{%4,%5,%6,%7},{%8,%9},{%0,%1,%2,%3};"
        : "+f"(c[0]), "+f"(c[1]), "+f"(c[2]), "+f"(c[3])
        : "r"(a0), "r"(a1), "r"(a2), "r"(a3), "r"(b0), "r"(b1));
}

// ---- persistent kernel ----
__global__ void __launch_bounds__(NTHREADS, 1)
SequenceModelPadded_kernel(
    const float* __restrict__ inp,        // (B,T,I)
    const void*  __restrict__ slen_raw,   // (B,) int64 OR int32
    const float* __restrict__ Wx,         // (T,H,I)
    const float* __restrict__ Wh,         // (T,H,H)
    const float* __restrict__ bias,       // (T,H)
    const float* __restrict__ Wout,       // (1,H)
    const float* __restrict__ bout,       // (1,)
    float* __restrict__ out)              // (B,1)
{
    extern __shared__ float sm[];
    __shared__ int s_is64;
    __shared__ int s_perm[256];
    __shared__ int s_lorig[256];
    __shared__ int s_lsorted[256];
    __shared__ int s_act[256];

    int tid  = threadIdx.x;
    int bx   = blockIdx.x;
    int half = bx >> 6;
    int lh   = bx & 63;
    int nblk = lh >> 2;          // 0..15 (N tile of 64 cols)
    int ks   = lh & 3;           // 0..3  (K split of 256)

    int lane = tid & 31, warp = tid >> 5;
    int wm = warp & 3, wn = warp >> 2;
    int g  = lane >> 2, tg = lane & 3;

    // ---- seq_lengths dtype sniff ----
    if (tid == 0) {
        const unsigned* w = (const unsigned*)slen_raw;
        unsigned z = 0;
        for (int i = 1; i < 256; i += 2) z |= __ldg(&w[i]);
        s_is64 = (z == 0) ? 1 : 0;
    }
    __syncthreads();
    const int is64 = s_is64;

    // ---- stable sort of lengths (descending) ----
    {
        int L = is64 ? (int)__ldg(&((const int*)slen_raw)[tid * 2])
                     : (int)__ldg(&((const int*)slen_raw)[tid]);
        s_lorig[tid] = L;
        __syncthreads();
        int rank = 0;
        for (int j = 0; j < 256; j++) {
            int Lj = s_lorig[j];
            rank += (Lj > L) || (Lj == L && j < tid);
        }
        s_perm[rank]    = tid;
        s_lsorted[rank] = L;
        __syncthreads();
        int a = 0;
        for (int rl = 0; rl < 128; rl++)
            a += (s_lsorted[2 * rl + half] > tid) ? 1 : 0;
        s_act[tid] = a;
        __syncthreads();
    }
    const int hmax = s_lsorted[half];

    // ---- zero BOTH h buffers ----
    for (int e = tid; e < 2048; e += NTHREADS) {
        g_h[0][bx * 2048 + e] = 0.f;
        g_h[1][bx * 2048 + e] = 0.f;
    }

    // ---- reset flags ----
    if (bx == 0 && tid == 0) {
        for (int i = 0; i < 16; i++) {
            g_pflag[0][i] = 0; g_pflag[1][i] = 0;
            g_hflag[0][i] = 0; g_hflag[1][i] = 0;
        }
    }

    // ============================================================
    // PROLOGUE: xpart[t, ss(r)] = x[perm[r], t] @ Wx[t]^T (act-scaled)
    // ============================================================
    for (int rep = 0; rep < 2; rep++) {
        int t = bx + rep * 128;
        int actp = 0;
        for (int j = 0; j < 256; j++) actp += (s_lsorted[j] > t) ? 1 : 0;
        if (actp == 0) continue;
        int actpL = (actp + 15) & ~15;

        for (int nt = 0; nt < 8; nt++) {
            float acc[4][8][4];
#pragma unroll
            for (int s = 0; s < 4; s++)
#pragma unroll
                for (int u = 0; u < 8; u++)
#pragma unroll
                    for (int q = 0; q < 4; q++) acc[s][u][q] = 0.f;

            {   // chunk 0
                float* pa = sm + P_A;
                float* pw = sm + P_W;
#pragma unroll
                for (int it = 0; it < 8; it++) {
                    int v = tid + NTHREADS * it; int row = v >> 3, seg = v & 7;
                    if (row < actpL) {
                        int pr = s_perm[row];
                        cpa(pa + row * 36 + seg * 4,
                            inp + (size_t)pr * (TT * II) + (size_t)t * II + seg * 4);
                    }
                }
#pragma unroll
                for (int it = 0; it < 4; it++) {
                    int v = tid + NTHREADS * it; int row = v >> 3, seg = v & 7;
                    cpa(pw + row * 36 + seg * 4,
                        Wx + ((size_t)t * HH + nt * 128 + row) * II + seg * 4);
                }
                CPCOMMIT();
            }
            for (int ch = 0; ch < 16; ch++) {
                if (ch < 15) {
                    int nb = (ch + 1) & 1;
                    float* pa = sm + P_A + nb * P_A_BUF;
                    float* pw = sm + P_W + nb * P_W_BUF;
                    int ko = (ch + 1) * 32;
#pragma unroll
                    for (int it = 0; it < 8; it++) {
                        int v = tid + NTHREADS * it; int row = v >> 3, seg = v & 7;
                        if (row < actpL) {
                            int pr = s_perm[row];
                            cpa(pa + row * 36 + seg * 4,
                                inp + (size_t)pr * (TT * II) + (size_t)t * II + ko + seg * 4);
                        }
                    }
#pragma unroll
                    for (int it = 0; it < 4; it++) {
                        int v = tid + NTHREADS * it; int row = v >> 3, seg = v & 7;
                        cpa(pw + row * 36 + seg * 4,
                            Wx + ((size_t)t * HH + nt * 128 + row) * II + ko + seg * 4);
                    }
                    CPCOMMIT();
                    CPWAIT(1);
                } else {
                    CPWAIT(0);
                }
                __syncthreads();
                const float* pa = sm + P_A + (ch & 1) * P_A_BUF;
                const float* pw = sm + P_W + (ch & 1) * P_W_BUF;
#pragma unroll
                for (int kk = 0; kk < 4; kk++) {
                    uint32_t ua[4][4];
#pragma unroll
                    for (int s = 0; s < 4; s++) {
                        if (wm * 64 + s * 16 < actp) {
                            int base = (wm * 64 + s * 16 + g) * 36 + kk * 8 + tg;
                            ua[s][0] = f2tf(pa[base]);
                            ua[s][1] = f2tf(pa[base + 8 * 36]);
                            ua[s][2] = f2tf(pa[base + 4]);
                            ua[s][3] = f2tf(pa[base + 8 * 36 + 4]);
                        }
                    }
#pragma unroll
                    for (int u = 0; u < 8; u++) {
                        int wb = (wn * 64 + u * 8 + g) * 36 + kk * 8 + tg;
                        uint32_t b0 = f2tf(pw[wb]);
                        uint32_t b1 = f2tf(pw[wb + 4]);
#pragma unroll
                        for (int s = 0; s < 4; s++)
                            if (wm * 64 + s * 16 < actp)
                                mma8(acc[s][u], ua[s][0], ua[s][1], ua[s][2], ua[s][3], b0, b1);
                    }
                }
                __syncthreads();
            }
#pragma unroll
            for (int s = 0; s < 4; s++) {
                if (wm * 64 + s * 16 >= actp) continue;
#pragma unroll
                for (int u = 0; u < 8; u++) {
                    int r0 = wm * 64 + s * 16 + g;
                    int r1 = r0 + 8;
                    int c  = nt * 128 + wn * 64 + u * 8 + 2 * tg;
                    int ss0 = ((r0 & 1) << 7) | (r0 >> 1);
                    int ss1 = ((r1 & 1) << 7) | (r1 >> 1);
                    *(float2*)(g_xpart + ((size_t)t * BB + ss0) * HH + c) =
                        make_float2(acc[s][u][0], acc[s][u][1]);
                    *(float2*)(g_xpart + ((size_t)t * BB + ss1) * HH + c) =
                        make_float2(acc[s][u][2], acc[s][u][3]);
                }
            }
        }
    }

    gbar(2, NCTA);   // xpart + h-init + flag reset globally visible

    // ============================================================
    // RECURRENT LOOP — wavefront flags + LDS.64 permuted feeds
    // ============================================================
    {   // prefetch step-0 W slice + bias into buffer 0
        float* ws = sm + L_W;
#pragma unroll
        for (int it = 0; it < 16; it++) {
            int v = tid + NTHREADS * it; int row = v >> 6, seg = v & 63;
            cpa(ws + row * 264 + seg * 4,
                Wh + ((size_t)nblk * 64 + row) * HH + ks * 256 + seg * 4);
        }
        if (tid < 4)
            cpa(sm + L_BI + tid * 4, bias + lh * 16 + tid * 4);
        CPCOMMIT();
    }

    for (int t = 0; t < hmax; t++) {
        int cur = t & 1;
        int nxt = cur ^ 1;
        int act      = s_act[t];
        int act_prev = (t == 0) ? 128 : s_act[t - 1];
        int actL = (act + 15) & ~15;
        unsigned htarget = 4u * (unsigned)t;

        // drain W prefetch; cvt + pair-permute W slice in place
        CPWAIT(0);
        __syncthreads();
        {
            uint32_t* wsu = (uint32_t*)(sm + L_W + cur * L_W_BUF);
#pragma unroll
            for (int it = 0; it < 8; it++) {
                int v = tid + NTHREADS * it;       // 0..2047 groups of 8
                int row = v >> 5, gi = v & 31;
                int base = row * 264 + gi * 8;
                uint4 q0 = *(uint4*)&wsu[base];
                uint4 q1 = *(uint4*)&wsu[base + 4];
                uint4 o0, o1;
                o0.x = f2tf(__uint_as_float(q0.x)); o0.y = f2tf(__uint_as_float(q1.x));
                o0.z = f2tf(__uint_as_float(q0.y)); o0.w = f2tf(__uint_as_float(q1.y));
                o1.x = f2tf(__uint_as_float(q0.z)); o1.y = f2tf(__uint_as_float(q1.z));
                o1.z = f2tf(__uint_as_float(q0.w)); o1.w = f2tf(__uint_as_float(q1.w));
                *(uint4*)&wsu[base]     = o0;
                *(uint4*)&wsu[base + 4] = o1;
            }
        }
        __syncthreads();
        const uint32_t* ws = (const uint32_t*)(sm + L_W + cur * L_W_BUF);
        const float* hbuf = g_h[cur];

        float acc[2][4][4];
#pragma unroll
        for (int s = 0; s < 2; s++)
#pragma unroll
            for (int u = 0; u < 4; u++)
#pragma unroll
                for (int q = 0; q < 4; q++) acc[s][u][q] = 0.f;

        {   // stage 0: wait its h group, issue load
            waitflag(&g_hflag[half][ks * 4], htarget);
            float* pa = sm + L_A;
            int ko = ks * 256;
#pragma unroll
            for (int it = 0; it < 8; it++) {
                int v = tid + NTHREADS * it; int row = v >> 4, seg = v & 15;
                if (row < actL)
                    cpa(pa + row * 72 + seg * 4,
                        hbuf + (size_t)(half * 128 + row) * HH + ko + seg * 4);
            }
            CPCOMMIT();
        }
        for (int j = 0; j < 4; j++) {
            if (j < 3) {
                waitflag(&g_hflag[half][ks * 4 + j + 1], htarget);
                float* pa = sm + L_A + ((j + 1) & 1) * L_A_BUF;
                int ko = ks * 256 + (j + 1) * 64;
#pragma unroll
                for (int it = 0; it < 8; it++) {
                    int v = tid + NTHREADS * it; int row = v >> 4, seg = v & 15;
                    if (row < actL)
                        cpa(pa + row * 72 + seg * 4,
                            hbuf + (size_t)(half * 128 + row) * HH + ko + seg * 4);
                }
                CPCOMMIT();
                CPWAIT(1);
            } else {
                CPWAIT(0);
            }
            __syncthreads();
            const uint32_t* pa = (const uint32_t*)(sm + L_A + (j & 1) * L_A_BUF);
#pragma unroll
            for (int kk = 0; kk < 8; kk++) {
                uint2 qa[2][2];
#pragma unroll
                for (int s = 0; s < 2; s++) {
                    if (wm * 32 + s * 16 < act) {
                        int base = (wm * 32 + s * 16 + g) * 72 + kk * 8 + 2 * tg;
                        qa[s][0] = *(const uint2*)&pa[base];
                        qa[s][1] = *(const uint2*)&pa[base + 8 * 72];
                    }
                }
#pragma unroll
                for (int u = 0; u < 4; u++) {
                    int wb = (wn * 32 + u * 8 + g) * 264 + j * 64 + kk * 8 + 2 * tg;
                    uint2 qb = *(const uint2*)&ws[wb];
#pragma unroll
                    for (int s = 0; s < 2; s++)
                        if (wm * 32 + s * 16 < act)
                            mma8(acc[s][u], qa[s][0].x, qa[s][1].x,
                                 qa[s][0].y, qa[s][1].y, qb.x, qb.y);
                }
            }
            __syncthreads();
        }

        {   // prefetch next step's W slice + bias
            int tn = (t + 1 < TT) ? (t + 1) : (TT - 1);
            float* wsn = sm + L_W + nxt * L_W_BUF;
#pragma unroll
            for (int it = 0; it < 16; it++) {
                int v = tid + NTHREADS * it; int row = v >> 6, seg = v & 63;
                cpa(wsn + row * 264 + seg * 4,
                    Wh + ((size_t)tn * HH + nblk * 64 + row) * HH + ks * 256 + seg * 4);
            }
            if (tid < 4)
                cpa(sm + L_BI + nxt * L_BI_BUF + tid * 4,
                    bias + (size_t)tn * HH + lh * 16 + tid * 4);
            CPCOMMIT();
        }

        {   // store split-K partial: own 16-col window -> smem, rest -> global
            float* P    = g_part[cur] + (size_t)(half * 64 + lh) * 8192;
            float* SOWN = sm + L_OWN;
            int wown = lh & 3;
#pragma unroll
            for (int s = 0; s < 2; s++) {
                if (wm * 32 + s * 16 >= act) continue;
#pragma unroll
                for (int u = 0; u < 4; u++) {
                    int r = wm * 32 + s * 16 + g;
                    int c = wn * 32 + u * 8 + 2 * tg;
                    float2 v0 = make_float2(acc[s][u][0], acc[s][u][1]);
                    float2 v1 = make_float2(acc[s][u][2], acc[s][u][3]);
                    if ((2 * wn + (u >> 1)) == wown) {
                        int cl = c - 16 * wown;
                        *(float2*)&SOWN[r * 18 + cl]       = v0;
                        *(float2*)&SOWN[(r + 8) * 18 + cl] = v1;
                    } else {
                        *(float2*)&P[r * 64 + c]       = v0;
                        *(float2*)&P[(r + 8) * 64 + c] = v1;
                    }
                }
            }
        }
        arrive(&g_pflag[half][nblk]);
        waitflag(&g_pflag[half][nblk], 4u * (unsigned)(t + 1));

        {   // reduce: own(smem) + 3 partials(L2) + xpart(L2) + bias -> tanh -> permuted h
            int r = tid >> 1;
            int c8  = (tid & 1) * 8;
            int cg_ = lh * 16 + c8;
            if (r < act) {
                const float* SOWN = sm + L_OWN;
                float v[8];
#pragma unroll
                for (int q = 0; q < 8; q++) v[q] = SOWN[r * 18 + c8 + q];
                int nb4 = lh & ~3;
#pragma unroll
                for (int ksp = 0; ksp < 4; ksp++) {
                    if (ksp == (lh & 3)) continue;
                    const float4* p = (const float4*)&g_part[cur][
                        (size_t)(half * 64 + nb4 + ksp) * 8192 + r * 64 + (cg_ & 63)];
                    float4 a = __ldcg(p);
                    float4 b = __ldcg(p + 1);
                    v[0] += a.x; v[1] += a.y; v[2] += a.z; v[3] += a.w;
                    v[4] += b.x; v[5] += b.y; v[6] += b.z; v[7] += b.w;
                }
                const float4* xp = (const float4*)&g_xpart[
                    ((size_t)t * BB + half * 128 + r) * HH + cg_];
                float4 xa = __ldcg(xp), xb = __ldcg(xp + 1);
                v[0] += xa.x; v[1] += xa.y; v[2] += xa.z; v[3] += xa.w;
                v[4] += xb.x; v[5] += xb.y; v[6] += xb.z; v[7] += xb.w;
                const float* bs = sm + L_BI + cur * L_BI_BUF + c8;
#pragma unroll
                for (int q = 0; q < 8; q++)
                    v[q] = __uint_as_float(f2tf(tanhf(v[q] + bs[q])));

                // pair-permuted write: (c0,c4,c1,c5) (c2,c6,c3,c7)
                float4* hp = (float4*)(g_h[nxt] + (size_t)(half * 128 + r) * HH + cg_);
                hp[0] = make_float4(v[0], v[4], v[1], v[5]);
                hp[1] = make_float4(v[2], v[6], v[3], v[7]);
            } else if (r < act_prev) {
                const float4* src = (const float4*)(g_h[cur] + (size_t)(half * 128 + r) * HH + cg_);
                float4* dst = (float4*)(g_h[nxt] + (size_t)(half * 128 + r) * HH + cg_);
                dst[0] = __ldcg(src);
                dst[1] = __ldcg(src + 1);
            }
        }
        arrive(&g_hflag[half][nblk]);
    }

    CPWAIT(0);
    gbar(half, HALFC);   // all h writes of this half visible

    // ---- output: h stored permuted -> map positions back to Wout cols ----
    const float* hfin = g_h[hmax & 1];
    float* red = sm;
#pragma unroll
    for (int rr = 0; rr < 2; rr++) {
        int rl = lh * 2 + rr;
        int gr = half * 128 + rl;
        int ob = s_perm[2 * rl + half];
        float p = 0.f;
        for (int pos = tid; pos < HH; pos += NTHREADS) {
            int c = (pos & ~7) + ((pos >> 1) & 3) + ((pos & 1) << 2);
            p += __ldcg(&hfin[(size_t)gr * HH + pos]) * __ldg(&Wout[c]);
        }
        red[tid] = p;
        __syncthreads();
        for (int s = 128; s > 0; s >>= 1) {
            if (tid < s) red[tid] += red[tid + s];
            __syncthreads();
        }
        if (tid == 0) out[ob] = red[0] + __ldg(&bout[0]);
        __syncthreads();
    }
}

extern "C" void kernel_launch(void* const* d_in, const int* in_sizes, int n_in,
                              void* d_out, int out_size) {
    (void)in_sizes; (void)n_in; (void)out_size;
    const float* inp  = (const float*)d_in[0];
    const void*  slen = (const void*)d_in[1];
    const float* Wx   = (const float*)d_in[2];
    const float* Wh   = (const float*)d_in[3];
    const float* bias = (const float*)d_in[4];
    const float* Wout = (const float*)d_in[5];
    const float* bout = (const float*)d_in[6];
    float*       out  = (float*)d_out;

    static int s_attr_done = 0;
    if (!s_attr_done) {
        cudaFuncSetAttribute(SequenceModelPadded_kernel,
                             cudaFuncAttributeMaxDynamicSharedMemorySize, SMEM_BYTES);
        s_attr_done = 1;
    }
    SequenceModelPadded_kernel<<<NCTA, NTHREADS, SMEM_BYTES>>>(
        inp, slen, Wx, Wh, bias, Wout, bout, out);
}